// round 12
// baseline (speedup 1.0000x reference)
#include <cuda_runtime.h>
#include <cuda_bf16.h>
#include <cstdint>

// Shapes (fixed by the problem)
#define BB 64      // batch
#define VV 64      // num nodes
#define DD 64      // input dim
#define HH 64      // hidden
#define EEDGES 4032
#define ETY 2
#define NJ 8       // receivers per block in msg_kernel (grid = 512 -> single wave)

// Scratch:
//   g_P  [b][v][h]   recv-side partial, bias folded (plain layout)
//   g_Qp [b][v][32]  send-side partial, PAIR-PACKED: pair cp holds
//                    (Q[v][(cp>>2)*8+(cp&3)], Q[v][(cp>>2)*8+(cp&3)+4])
__device__ float  g_P [BB * VV * HH];
__device__ float2 g_Qp[BB * VV * 32];

// ---------------------------------------------------------------------------
// Kernel A: per-node precompute (fp32, exact).
//   P[b,v,h] = sum_d inputs[b,v,d] * W1[1][h, d]      + b1[1][h]
//   Q[b,v,h] = sum_d inputs[b,v,d] * W1[1][h, 64+d]   (stored pair-packed)
// ---------------------------------------------------------------------------
__global__ __launch_bounds__(128) void prep_kernel(
    const float* __restrict__ inputs,
    const float* __restrict__ W1,
    const float* __restrict__ b1)
{
    const int b    = blockIdx.x;
    const int half = blockIdx.y;   // 0 -> P, 1 -> Q
    const int t    = threadIdx.x;

    __shared__ float XT[64 * 65];  // XT[d][v]
    __shared__ float WT[64 * 65];  // WT[d][h] = W1[1][h][half*64+d]

    const float4* in4 = reinterpret_cast<const float4*>(inputs) + b * 1024;
    #pragma unroll
    for (int s = 0; s < 8; s++) {
        int item = t + 128 * s;            // 1024 float4
        int v = item >> 4, d4 = item & 15;
        float4 x = in4[v * 16 + d4];
        XT[(4 * d4 + 0) * 65 + v] = x.x;
        XT[(4 * d4 + 1) * 65 + v] = x.y;
        XT[(4 * d4 + 2) * 65 + v] = x.z;
        XT[(4 * d4 + 3) * 65 + v] = x.w;
    }
    const float4* w14 = reinterpret_cast<const float4*>(W1);
    #pragma unroll
    for (int s = 0; s < 8; s++) {
        int item = t + 128 * s;
        int h = item >> 4, d4 = item & 15;
        float4 w = w14[2048 + h * 32 + half * 16 + d4]; // W1[1][h][half*64 + 4*d4]
        WT[(4 * d4 + 0) * 65 + h] = w.x;
        WT[(4 * d4 + 1) * 65 + h] = w.y;
        WT[(4 * d4 + 2) * 65 + h] = w.z;
        WT[(4 * d4 + 3) * 65 + h] = w.w;
    }
    __syncthreads();

    const int tx = t & 15, ty = t >> 4;
    const int r0 = ty * 8, k0 = tx * 4;    // rows = v, cols = h
    float acc[8][4];
    #pragma unroll
    for (int rr = 0; rr < 8; rr++)
        #pragma unroll
        for (int cc = 0; cc < 4; cc++) acc[rr][cc] = 0.f;

    #pragma unroll 4
    for (int kk = 0; kk < 64; kk++) {
        float a[8], bv[4];
        #pragma unroll
        for (int u = 0; u < 8; u++) a[u] = XT[kk * 65 + r0 + u];
        #pragma unroll
        for (int u = 0; u < 4; u++) bv[u] = WT[kk * 65 + k0 + u];
        #pragma unroll
        for (int rr = 0; rr < 8; rr++)
            #pragma unroll
            for (int cc = 0; cc < 4; cc++)
                acc[rr][cc] = fmaf(a[rr], bv[cc], acc[rr][cc]);
    }

    if (half == 0) {
        #pragma unroll
        for (int rr = 0; rr < 8; rr++) {
            int v = r0 + rr;
            #pragma unroll
            for (int cc = 0; cc < 4; cc++) {
                int h = k0 + cc;
                g_P[(b * 64 + v) * 64 + h] = acc[rr][cc] + b1[64 + h];
            }
        }
    } else {
        // Stage plain [v][h] in smem (reuse XT), then emit pair-packed
        __syncthreads();
        #pragma unroll
        for (int rr = 0; rr < 8; rr++)
            #pragma unroll
            for (int cc = 0; cc < 4; cc++)
                XT[(r0 + rr) * 65 + (k0 + cc)] = acc[rr][cc];
        __syncthreads();
        float2* dst = g_Qp + b * 2048;
        #pragma unroll
        for (int s = 0; s < 16; s++) {
            int idx = t + 128 * s;          // 2048 pairs
            int v = idx >> 5, cp = idx & 31;
            int h0 = (cp >> 2) * 8 + (cp & 3);
            dst[idx] = make_float2(XT[v * 65 + h0], XT[v * 65 + h0 + 4]);
        }
    }
}

// ---------------------------------------------------------------------------
// tf32 mma.sync m16n8k8 (row.col, fp32 accumulate)
//   A: a0=(g,tig) a1=(g+8,tig) a2=(g,tig+4) a3=(g+8,tig+4)
//   B: b0=(k=tig,n=g) b1=(k=tig+4,n=g)
//   C: c0=(g,2t) c1=(g,2t+1) c2=(g+8,2t) c3=(g+8,2t+1)
// A operands carry raw fp32 bit patterns; HMMA.TF32 uses only the tf32 bits
// (truncation). B stays rna-rounded (one-time).
// ---------------------------------------------------------------------------
__device__ __forceinline__ void mma_tf32(
    float& c0, float& c1, float& c2, float& c3,
    uint32_t a0, uint32_t a1, uint32_t a2, uint32_t a3,
    uint32_t b0, uint32_t b1)
{
    asm volatile(
        "mma.sync.aligned.m16n8k8.row.col.f32.tf32.tf32.f32 "
        "{%0,%1,%2,%3},{%4,%5,%6,%7},{%8,%9},{%0,%1,%2,%3};"
        : "+f"(c0), "+f"(c1), "+f"(c2), "+f"(c3)
        : "r"(a0), "r"(a1), "r"(a2), "r"(a3), "r"(b0), "r"(b1));
}

__device__ __forceinline__ uint32_t f2tf32(float v)
{
    uint32_t r;
    asm("cvt.rna.tf32.f32 %0, %1;" : "=r"(r) : "f"(v));
    return r;
}

// Packed fp32 pair add
__device__ __forceinline__ float2 add_f32x2(float2 a, float2 b)
{
    unsigned long long r, x, y;
    x = *reinterpret_cast<unsigned long long*>(&a);
    y = *reinterpret_cast<unsigned long long*>(&b);
    asm("add.rn.f32x2 %0, %1, %2;" : "=l"(r) : "l"(x), "l"(y));
    return *reinterpret_cast<float2*>(&r);
}

// ---------------------------------------------------------------------------
// Kernel B: one block (256 threads = 8 warps) per (b, group of NJ receivers).
// Warp w computes C[0:64][8w:8w+8] — 8-col slices so B fragments are tiny
// (16 regs) and regs stay <=64 -> 4 blocks/SM (32 warps) at grid 512 = single
// wave at ~43% occupancy. Hm in pair-packed smem (stride-36 float2,
// conflict-free LDS.64). Per-j scalars register-prefetched during prior GEMM.
// ---------------------------------------------------------------------------
__global__ __launch_bounds__(256, 4) void msg_kernel(
    const float* __restrict__ inputs,
    const float* __restrict__ edges,
    const float* __restrict__ W2,
    const float* __restrict__ b2,
    float* __restrict__ out)
{
    __shared__ __align__(16) float2 Hmp[64 * 36];   // Hm pairs (raw fp32)
    __shared__ float Ps[2][64], ews[2][64];         // double-buffered per j

    const int j0 = blockIdx.x * NJ;
    const int b  = blockIdx.y;
    const int t  = threadIdx.x;
    const int w    = t >> 5;         // 0..7
    const int lane = t & 31;
    const int g    = lane >> 2;      // groupID
    const int tig  = lane & 3;       // thread-in-group

    // j-invariant W2 B-fragments (rna tf32, one-time) and b2 in registers.
    // Warp w covers output cols [8w, 8w+8).
    uint32_t breg[8][2];
    {
        const int o = 8 * w + g;
        const float* wrow = W2 + 4096 + o * 64;
        #pragma unroll
        for (int ks = 0; ks < 8; ks++) {
            breg[ks][0] = f2tf32(__ldg(&wrow[ks * 8 + tig]));
            breg[ks][1] = f2tf32(__ldg(&wrow[ks * 8 + tig + 4]));
        }
    }
    float b2r[2];
    #pragma unroll
    for (int cc = 0; cc < 2; cc++)
        b2r[cc] = __ldg(&b2[64 + 8 * w + 2 * tig + cc]);

    const float2* qp = g_Qp + b * 2048;

    // Prologue prefetch of j0's scalars
    float rP = 0.f, rEw = 0.f, rInp = 0.f;
    if (t < 64) {
        rP   = g_P[(b * 64 + j0) * 64 + t];
        rInp = inputs[(b * 64 + j0) * 64 + t];
        if (t < 63) {
            int i = t + (t >= j0 ? 1 : 0);
            int e = i * 63 + (j0 < i ? j0 : j0 - 1);
            rEw = __ldg(&edges[(b * EEDGES + e) * ETY + 1]);
        }
    }

    for (int jj = 0; jj < NJ; jj++) {
        const int j = j0 + jj;
        const int buf = jj & 1;

        if (t < 64) {                      // commit prefetched scalars
            Ps[buf][t]  = rP;
            ews[buf][t] = rEw;
        }
        __syncthreads();   // S1: scalars visible; all warps done with Hmp (prev j)

        // Build Hmp: warp w owns rows [8w, 8w+8); lane owns pair cp=lane.
        {
            const int cp = lane;
            const int h0 = (cp >> 2) * 8 + (cp & 3);
            const float2 p = make_float2(Ps[buf][h0], Ps[buf][h0 + 4]);
            #pragma unroll
            for (int rr = 0; rr < 8; rr++) {
                int r = 8 * w + rr;
                int i = (r < 63) ? (r + (r >= j ? 1 : 0)) : 0;   // pad row -> ew 0
                float2 s = add_f32x2(p, __ldg(&qp[i * 32 + cp]));
                Hmp[r * 36 + cp] = make_float2(fmaxf(s.x, 0.f), fmaxf(s.y, 0.f));
            }
        }
        __syncthreads();   // S2: Hmp ready

        // Passthrough write + prefetch next j (LDG latency overlaps GEMM)
        if (t < 64) {
            out[(b * 64 + j) * (DD + HH) + t] = rInp;
            if (jj + 1 < NJ) {
                const int jn = j + 1;
                rP   = g_P[(b * 64 + jn) * 64 + t];
                rInp = inputs[(b * 64 + jn) * 64 + t];
                rEw = 0.f;
                if (t < 63) {
                    int i = t + (t >= jn ? 1 : 0);
                    int e = i * 63 + (jn < i ? jn : jn - 1);
                    rEw = __ldg(&edges[(b * EEDGES + e) * ETY + 1]);
                }
            }
        }

        // GEMM: C[0:64][8w:8w+8] via 8 k-steps x 4 m-blocks
        float acc[4][4];
        #pragma unroll
        for (int mb = 0; mb < 4; mb++)
            #pragma unroll
            for (int cc = 0; cc < 4; cc++) acc[mb][cc] = 0.f;

        #pragma unroll
        for (int ks = 0; ks < 8; ks++) {
            const int pp = ks * 4 + tig;
            #pragma unroll
            for (int mb = 0; mb < 4; mb++) {
                float2 aLo = Hmp[(16 * mb + g) * 36 + pp];       // (a0, a2)
                float2 aHi = Hmp[(16 * mb + 8 + g) * 36 + pp];   // (a1, a3)
                mma_tf32(acc[mb][0], acc[mb][1], acc[mb][2], acc[mb][3],
                         __float_as_uint(aLo.x), __float_as_uint(aHi.x),
                         __float_as_uint(aLo.y), __float_as_uint(aHi.y),
                         breg[ks][0], breg[ks][1]);
            }
        }

        // Epilogue: relu(C + b2) * ew, reduce over all 64 rows
        float part[2] = {0.f, 0.f};
        #pragma unroll
        for (int mb = 0; mb < 4; mb++) {
            const float w1 = ews[buf][16 * mb + g];
            const float w2 = ews[buf][16 * mb + 8 + g];
            #pragma unroll
            for (int cc = 0; cc < 2; cc++) {
                part[cc] +=
                    fmaxf(acc[mb][cc]     + b2r[cc], 0.f) * w1 +
                    fmaxf(acc[mb][2 + cc] + b2r[cc], 0.f) * w2;
            }
        }
        // shfl-tree over groupID: lanes 0..3 (tig) hold column sums
        #pragma unroll
        for (int off = 16; off >= 4; off >>= 1)
            #pragma unroll
            for (int p = 0; p < 2; p++)
                part[p] += __shfl_down_sync(0xffffffffu, part[p], off);

        if (lane < 4) {
            float* orow = out + (b * 64 + j) * (DD + HH) + 64 + 8 * w;
            #pragma unroll
            for (int cc = 0; cc < 2; cc++)
                orow[2 * lane + cc] = part[cc];
        }
        // No trailing barrier: next S1 orders Hmp reuse; scalar buffers alternate.
    }
}

extern "C" void kernel_launch(void* const* d_in, const int* in_sizes, int n_in,
                              void* d_out, int out_size)
{
    const float* inputs = (const float*)d_in[0];
    const float* edges  = (const float*)d_in[1];
    const float* W1     = (const float*)d_in[2];
    const float* b1     = (const float*)d_in[3];
    const float* W2     = (const float*)d_in[4];
    const float* b2     = (const float*)d_in[5];
    // d_in[6]=send_idx, d_in[7]=recv_idx: complete-minus-diagonal, handled analytically
    float* out = (float*)d_out;

    dim3 gridA(BB, 2);
    prep_kernel<<<gridA, 128>>>(inputs, W1, b1);

    dim3 gridB(VV / NJ, BB);  // (j-group, b) = (8, 64) = 512 blocks
    msg_kernel<<<gridB, 256>>>(inputs, edges, W2, b2, out);
}

// round 14
// speedup vs baseline: 1.1406x; 1.1406x over previous
#include <cuda_runtime.h>
#include <cuda_bf16.h>
#include <cstdint>

// Shapes (fixed by the problem)
#define BB 64      // batch
#define VV 64      // num nodes
#define DD 64      // input dim
#define HH 64      // hidden
#define EEDGES 4032
#define ETY 2
#define NJ 8       // receivers per block in msg_kernel (grid = 512 -> single wave)

// Scratch:
//   g_P  [b][v][h]   recv-side partial, bias folded (plain layout)
//   g_Qp [b][v][32]  send-side partial, PAIR-PACKED: pair cp holds
//                    (Q[v][(cp>>2)*8+(cp&3)], Q[v][(cp>>2)*8+(cp&3)+4])
__device__ float  g_P [BB * VV * HH];
__device__ float2 g_Qp[BB * VV * 32];

// ---------------------------------------------------------------------------
// Kernel A: per-node precompute (fp32, exact).
//   P[b,v,h] = sum_d inputs[b,v,d] * W1[1][h, d]      + b1[1][h]
//   Q[b,v,h] = sum_d inputs[b,v,d] * W1[1][h, 64+d]   (stored pair-packed)
// ---------------------------------------------------------------------------
__global__ __launch_bounds__(128) void prep_kernel(
    const float* __restrict__ inputs,
    const float* __restrict__ W1,
    const float* __restrict__ b1)
{
    const int b    = blockIdx.x;
    const int half = blockIdx.y;   // 0 -> P, 1 -> Q
    const int t    = threadIdx.x;

    __shared__ float XT[64 * 65];  // XT[d][v]
    __shared__ float WT[64 * 65];  // WT[d][h] = W1[1][h][half*64+d]

    const float4* in4 = reinterpret_cast<const float4*>(inputs) + b * 1024;
    #pragma unroll
    for (int s = 0; s < 8; s++) {
        int item = t + 128 * s;            // 1024 float4
        int v = item >> 4, d4 = item & 15;
        float4 x = in4[v * 16 + d4];
        XT[(4 * d4 + 0) * 65 + v] = x.x;
        XT[(4 * d4 + 1) * 65 + v] = x.y;
        XT[(4 * d4 + 2) * 65 + v] = x.z;
        XT[(4 * d4 + 3) * 65 + v] = x.w;
    }
    const float4* w14 = reinterpret_cast<const float4*>(W1);
    #pragma unroll
    for (int s = 0; s < 8; s++) {
        int item = t + 128 * s;
        int h = item >> 4, d4 = item & 15;
        float4 w = w14[2048 + h * 32 + half * 16 + d4]; // W1[1][h][half*64 + 4*d4]
        WT[(4 * d4 + 0) * 65 + h] = w.x;
        WT[(4 * d4 + 1) * 65 + h] = w.y;
        WT[(4 * d4 + 2) * 65 + h] = w.z;
        WT[(4 * d4 + 3) * 65 + h] = w.w;
    }
    __syncthreads();

    const int tx = t & 15, ty = t >> 4;
    const int r0 = ty * 8, k0 = tx * 4;    // rows = v, cols = h
    float acc[8][4];
    #pragma unroll
    for (int rr = 0; rr < 8; rr++)
        #pragma unroll
        for (int cc = 0; cc < 4; cc++) acc[rr][cc] = 0.f;

    #pragma unroll 4
    for (int kk = 0; kk < 64; kk++) {
        float a[8], bv[4];
        #pragma unroll
        for (int u = 0; u < 8; u++) a[u] = XT[kk * 65 + r0 + u];
        #pragma unroll
        for (int u = 0; u < 4; u++) bv[u] = WT[kk * 65 + k0 + u];
        #pragma unroll
        for (int rr = 0; rr < 8; rr++)
            #pragma unroll
            for (int cc = 0; cc < 4; cc++)
                acc[rr][cc] = fmaf(a[rr], bv[cc], acc[rr][cc]);
    }

    if (half == 0) {
        #pragma unroll
        for (int rr = 0; rr < 8; rr++) {
            int v = r0 + rr;
            #pragma unroll
            for (int cc = 0; cc < 4; cc++) {
                int h = k0 + cc;
                g_P[(b * 64 + v) * 64 + h] = acc[rr][cc] + b1[64 + h];
            }
        }
    } else {
        // Stage plain [v][h] in smem (reuse XT), then emit pair-packed
        __syncthreads();
        #pragma unroll
        for (int rr = 0; rr < 8; rr++)
            #pragma unroll
            for (int cc = 0; cc < 4; cc++)
                XT[(r0 + rr) * 65 + (k0 + cc)] = acc[rr][cc];
        __syncthreads();
        float2* dst = g_Qp + b * 2048;
        #pragma unroll
        for (int s = 0; s < 16; s++) {
            int idx = t + 128 * s;          // 2048 pairs
            int v = idx >> 5, cp = idx & 31;
            int h0 = (cp >> 2) * 8 + (cp & 3);
            dst[idx] = make_float2(XT[v * 65 + h0], XT[v * 65 + h0 + 4]);
        }
    }
}

// ---------------------------------------------------------------------------
// tf32 mma.sync m16n8k8 (row.col, fp32 accumulate)
//   A: a0=(g,tig) a1=(g+8,tig) a2=(g,tig+4) a3=(g+8,tig+4)
//   B: b0=(k=tig,n=g) b1=(k=tig+4,n=g)
//   C: c0=(g,2t) c1=(g,2t+1) c2=(g+8,2t) c3=(g+8,2t+1)
// A operands carry raw fp32 bit patterns; HMMA.TF32 uses only the tf32 bits
// (truncation). B stays rna-rounded (one-time).
// ---------------------------------------------------------------------------
__device__ __forceinline__ void mma_tf32(
    float& c0, float& c1, float& c2, float& c3,
    uint32_t a0, uint32_t a1, uint32_t a2, uint32_t a3,
    uint32_t b0, uint32_t b1)
{
    asm volatile(
        "mma.sync.aligned.m16n8k8.row.col.f32.tf32.tf32.f32 "
        "{%0,%1,%2,%3},{%4,%5,%6,%7},{%8,%9},{%0,%1,%2,%3};"
        : "+f"(c0), "+f"(c1), "+f"(c2), "+f"(c3)
        : "r"(a0), "r"(a1), "r"(a2), "r"(a3), "r"(b0), "r"(b1));
}

__device__ __forceinline__ uint32_t f2tf32(float v)
{
    uint32_t r;
    asm("cvt.rna.tf32.f32 %0, %1;" : "=r"(r) : "f"(v));
    return r;
}

// Packed fp32 pair add
__device__ __forceinline__ float2 add_f32x2(float2 a, float2 b)
{
    unsigned long long r, x, y;
    x = *reinterpret_cast<unsigned long long*>(&a);
    y = *reinterpret_cast<unsigned long long*>(&b);
    asm("add.rn.f32x2 %0, %1, %2;" : "=l"(r) : "l"(x), "l"(y));
    return *reinterpret_cast<float2*>(&r);
}

// ---------------------------------------------------------------------------
// Kernel B: one block (128 threads = 4 warps) per (b, group of NJ receivers).
// R10 partition (proven fastest): warp w computes C[0:64][16w:16w+16], W2
// B-fragments in registers, Hm in pair-packed smem (stride-36 float2).
// One-barrier pipeline: Hmp double-buffered (jj&1), scalars triple-buffered
// (jj%3); the single S2 barrier per iteration orders everything:
//   - build(jj+1) vs GEMM(jj-1) on the shared Hmp buffer is ordered
//     transitively through S2(jj) (each warp passes S2 only after its GEMM).
//   - commit(jj+1) writes scalars[(jj+1)%3]; concurrent readers use
//     [jj%3] (build/epilogue) and [(jj-1)%3] — all distinct mod 3.
// ---------------------------------------------------------------------------
__global__ __launch_bounds__(128, 4) void msg_kernel(
    const float* __restrict__ inputs,
    const float* __restrict__ edges,
    const float* __restrict__ W2,
    const float* __restrict__ b2,
    float* __restrict__ out)
{
    __shared__ __align__(16) float2 Hmp[2][64 * 36];  // Hm pairs (raw fp32)
    __shared__ float Ps[3][64], ews[3][64];           // triple-buffered per j

    const int j0 = blockIdx.x * NJ;
    const int b  = blockIdx.y;
    const int t  = threadIdx.x;
    const int w    = t >> 5;
    const int lane = t & 31;
    const int g    = lane >> 2;      // groupID
    const int tig  = lane & 3;       // thread-in-group

    // j-invariant W2 B-fragments (rna tf32, one-time) and b2 in registers.
    uint32_t breg[2][8][2];
    #pragma unroll
    for (int nb = 0; nb < 2; nb++) {
        const int o = 16 * w + nb * 8 + g;
        const float* wrow = W2 + 4096 + o * 64;
        #pragma unroll
        for (int ks = 0; ks < 8; ks++) {
            breg[nb][ks][0] = f2tf32(__ldg(&wrow[ks * 8 + tig]));
            breg[nb][ks][1] = f2tf32(__ldg(&wrow[ks * 8 + tig + 4]));
        }
    }
    float b2r[2][2];
    #pragma unroll
    for (int nb = 0; nb < 2; nb++)
        #pragma unroll
        for (int cc = 0; cc < 2; cc++)
            b2r[nb][cc] = __ldg(&b2[64 + 16 * w + nb * 8 + 2 * tig + cc]);

    const float2* qp = g_Qp + b * 2048;

    // Prologue: commit j0 scalars + passthrough; prefetch j1 into registers.
    float rP = 0.f, rEw = 0.f, rInp = 0.f;
    if (t < 64) {
        float p0 = g_P[(b * 64 + j0) * 64 + t];
        float i0 = inputs[(b * 64 + j0) * 64 + t];
        float e0 = 0.f;
        if (t < 63) {
            int i = t + (t >= j0 ? 1 : 0);
            int e = i * 63 + (j0 < i ? j0 : j0 - 1);
            e0 = __ldg(&edges[(b * EEDGES + e) * ETY + 1]);
        }
        Ps[0][t] = p0;
        ews[0][t] = e0;
        out[(b * 64 + j0) * (DD + HH) + t] = i0;
        {   // prefetch j0+1
            const int jn = j0 + 1;
            rP   = g_P[(b * 64 + jn) * 64 + t];
            rInp = inputs[(b * 64 + jn) * 64 + t];
            if (t < 63) {
                int i = t + (t >= jn ? 1 : 0);
                int e = i * 63 + (jn < i ? jn : jn - 1);
                rEw = __ldg(&edges[(b * EEDGES + e) * ETY + 1]);
            }
        }
    }
    __syncthreads();   // S0: scalars(j0) visible

    for (int jj = 0; jj < NJ; jj++) {
        const int j  = j0 + jj;
        const int hb = jj & 1;          // Hmp buffer
        const int sb = jj % 3;          // scalar buffer
        float2* Hm = Hmp[hb];

        // Build Hm: warp w owns rows [16w,16w+16); lane owns pair cp=lane.
        {
            const int cp = lane;
            const int h0 = (cp >> 2) * 8 + (cp & 3);
            const float2 p = make_float2(Ps[sb][h0], Ps[sb][h0 + 4]);
            #pragma unroll
            for (int rr = 0; rr < 16; rr++) {
                int r = 16 * w + rr;
                int i = (r < 63) ? (r + (r >= j ? 1 : 0)) : 0;   // pad row -> ew 0
                float2 s = add_f32x2(p, __ldg(&qp[i * 32 + cp]));
                Hm[r * 36 + cp] = make_float2(fmaxf(s.x, 0.f), fmaxf(s.y, 0.f));
            }
        }

        // Commit next j's scalars (prefetched last iter) + passthrough write.
        if (t < 64 && jj + 1 < NJ) {
            const int sbn = (jj + 1) % 3;
            Ps[sbn][t]  = rP;
            ews[sbn][t] = rEw;
            out[(b * 64 + j + 1) * (DD + HH) + t] = rInp;
        }
        __syncthreads();   // S2: Hm(jj) + scalars(jj+1) visible

        // Prefetch j+2 scalars (LDG latency overlaps GEMM)
        if (t < 64 && jj + 2 < NJ) {
            const int jn = j + 2;
            rP   = g_P[(b * 64 + jn) * 64 + t];
            rInp = inputs[(b * 64 + jn) * 64 + t];
            rEw = 0.f;
            if (t < 63) {
                int i = t + (t >= jn ? 1 : 0);
                int e = i * 63 + (jn < i ? jn : jn - 1);
                rEw = __ldg(&edges[(b * EEDGES + e) * ETY + 1]);
            }
        }

        // GEMM: C[0:64][16w:16w+16] via 8 k-steps x 4 m-blocks x 2 n-blocks
        float acc[4][2][4];
        #pragma unroll
        for (int mb = 0; mb < 4; mb++)
            #pragma unroll
            for (int nb = 0; nb < 2; nb++)
                #pragma unroll
                for (int cc = 0; cc < 4; cc++) acc[mb][nb][cc] = 0.f;

        #pragma unroll
        for (int ks = 0; ks < 8; ks++) {
            const int pp = ks * 4 + tig;
            #pragma unroll
            for (int mb = 0; mb < 4; mb++) {
                float2 aLo = Hm[(16 * mb + g) * 36 + pp];       // (a0, a2)
                float2 aHi = Hm[(16 * mb + 8 + g) * 36 + pp];   // (a1, a3)
                uint32_t a0 = __float_as_uint(aLo.x);
                uint32_t a1 = __float_as_uint(aHi.x);
                uint32_t a2 = __float_as_uint(aLo.y);
                uint32_t a3 = __float_as_uint(aHi.y);
                #pragma unroll
                for (int nb = 0; nb < 2; nb++)
                    mma_tf32(acc[mb][nb][0], acc[mb][nb][1],
                             acc[mb][nb][2], acc[mb][nb][3],
                             a0, a1, a2, a3,
                             breg[nb][ks][0], breg[nb][ks][1]);
            }
        }

        // Epilogue: relu(C + b2) * ew, reduce over all 64 rows
        float part[4] = {0.f, 0.f, 0.f, 0.f};
        #pragma unroll
        for (int mb = 0; mb < 4; mb++) {
            const float w1 = ews[sb][16 * mb + g];
            const float w2 = ews[sb][16 * mb + 8 + g];
            #pragma unroll
            for (int nb = 0; nb < 2; nb++)
                #pragma unroll
                for (int cc = 0; cc < 2; cc++) {
                    float bo = b2r[nb][cc];
                    part[nb * 2 + cc] +=
                        fmaxf(acc[mb][nb][cc]     + bo, 0.f) * w1 +
                        fmaxf(acc[mb][nb][2 + cc] + bo, 0.f) * w2;
                }
        }
        // shfl-tree over groupID: lanes 0..3 (tig) hold column sums
        #pragma unroll
        for (int off = 16; off >= 4; off >>= 1)
            #pragma unroll
            for (int p = 0; p < 4; p++)
                part[p] += __shfl_down_sync(0xffffffffu, part[p], off);

        if (lane < 4) {
            float* orow = out + (b * 64 + j) * (DD + HH) + 64 + 16 * w;
            #pragma unroll
            for (int nb = 0; nb < 2; nb++)
                #pragma unroll
                for (int cc = 0; cc < 2; cc++)
                    orow[nb * 8 + 2 * lane + cc] = part[nb * 2 + cc];
        }
        // No trailing barrier: next build targets the other Hmp buffer; the
        // next S2 re-synchronizes. Scalar buffers rotate mod 3.
    }
}

extern "C" void kernel_launch(void* const* d_in, const int* in_sizes, int n_in,
                              void* d_out, int out_size)
{
    const float* inputs = (const float*)d_in[0];
    const float* edges  = (const float*)d_in[1];
    const float* W1     = (const float*)d_in[2];
    const float* b1     = (const float*)d_in[3];
    const float* W2     = (const float*)d_in[4];
    const float* b2     = (const float*)d_in[5];
    // d_in[6]=send_idx, d_in[7]=recv_idx: complete-minus-diagonal, handled analytically
    float* out = (float*)d_out;

    dim3 gridA(BB, 2);
    prep_kernel<<<gridA, 128>>>(inputs, W1, b1);

    dim3 gridB(VV / NJ, BB);  // (j-group, b) = (8, 64) = 512 blocks
    msg_kernel<<<gridB, 128>>>(inputs, edges, W2, b2, out);
}